// round 5
// baseline (speedup 1.0000x reference)
#include <cuda_runtime.h>
#include <cuda_bf16.h>
#include <cstdint>

// TemporalCooccurrenceMatrix — round 5: bucket-by-node-value pair-list scatter.
//
// C[b,w1,w2] = sum over valid same-node position pairs of
//              e^{-(l1-l2)^2/4} * e^{-|t1-t2|/5};   out = tanh(min(C,10)).
// All contributing pairs lie within a (batch, node-value) bucket (mean n=64).
// prep:     detect dtypes, compute (e^{+t/5}, e^{-t/5}), scatter valid positions
//           into 256 buckets via global atomics.
// pairs:    per bucket, enumerate n(n+1)/2 pairs with uniform control flow,
//           RED one canonical upper-triangle cell per pair.
// finalize: tanh + symmetric mirror into d_out, AND re-zero scratch+counters
//           so the next graph replay starts clean (statics are zero-init for call 1).

#define BPREP 256
#define TOTPOS 20480            // 8*128*20
#define NBKT  256               // 8 batches * 32 values
#define BCAP  128               // bucket capacity (mean 64, sd ~8)

__device__ float        g_acc[131072];        // [8][128][128] canonical cells only
__device__ int          g_cnt[NBKT];
__device__ float2       g_be [NBKT * BCAP];   // (e^{+t/5}, e^{-t/5})
__device__ unsigned int g_bwl[NBKT * BCAP];   // w | (l<<8)

// ---------------- prep: dtype detect + exp precompute + bucket scatter ----------------
__global__ __launch_bounds__(BPREP)
void prep_kernel(const void* __restrict__ nodes_raw,
                 const void* __restrict__ masks_raw,
                 const float* __restrict__ times)
{
    __shared__ int s_n64, s_m32;
    if (threadIdx.x < 32) {
        const unsigned int*  nw = (const unsigned int*)nodes_raw;
        const unsigned char* mb = (const unsigned char*)masks_raw;
        int lane = threadIdx.x;
        unsigned int oddw = nw[2 * lane + 1];            // int64 hi words all 0
        unsigned char b0 = mb[lane], b1 = mb[32 + lane]; // int32-bool: k%4!=0 bytes 0
        int nviol = (oddw != 0u);
        int mviol = (((lane & 3) != 0) && b0 != 0) |
                    ((((32 + lane) & 3) != 0) && b1 != 0);
        unsigned int vn = __ballot_sync(0xFFFFFFFFu, nviol);
        unsigned int vm = __ballot_sync(0xFFFFFFFFu, mviol);
        if (lane == 0) { s_n64 = (vn == 0u); s_m32 = (vm == 0u); }
    }
    __syncthreads();

    const int i = blockIdx.x * BPREP + threadIdx.x;
    if (i >= TOTPOS) return;

    const unsigned int*  n32p = (const unsigned int*)nodes_raw;
    const unsigned char* mbp  = (const unsigned char*)masks_raw;
    const unsigned int*  m32p = (const unsigned int*)masks_raw;

    bool m = s_m32 ? (m32p[i] != 0u) : (mbp[i] != 0);
    if (!m) return;

    int v = (int)(s_n64 ? n32p[i * 2] : n32p[i]) & 31;
    int b = i / 2560;
    int w = (i - b * 2560) / 20;
    int l = i % 20;

    float t  = times[i] * 0.2f;
    int bkt  = b * 32 + v;
    int idx  = atomicAdd(&g_cnt[bkt], 1);
    if (idx < BCAP) {
        g_be [bkt * BCAP + idx] = make_float2(__expf(t), __expf(-t));
        g_bwl[bkt * BCAP + idx] = (unsigned int)w | ((unsigned int)l << 8);
    }
}

// ---------------- pairs: uniform-flow triangular enumeration + RED scatter ----------------
__global__ __launch_bounds__(256)
void pairs_kernel()
{
    const int bkt = blockIdx.x >> 1;     // 0..255
    const int sub = blockIdx.x & 1;      // split each bucket across 2 CTAs
    const int b   = bkt >> 5;
    const int tid = threadIdx.x;

    __shared__ float2       se[BCAP];
    __shared__ unsigned int swl[BCAP];
    __shared__ float        dvals[20];
    __shared__ int          sn;

    if (tid == 0) sn = min(g_cnt[bkt], BCAP);
    if (tid < 20) dvals[tid] = __expf(-0.25f * (float)(tid * tid));
    __syncthreads();
    const int n = sn;
    for (int k = tid; k < n; k += 256) {
        se[k]  = g_be [bkt * BCAP + k];
        swl[k] = g_bwl[bkt * BCAP + k];
    }
    __syncthreads();

    const int   T   = n * (n + 1) / 2;
    const float fn2 = (float)(2 * n + 1);
    float* accb = g_acc + b * 16384;

    for (int p = sub * 256 + tid; p < T; p += 512) {
        // decode triangular pair index p -> (i <= j), row i starts at R(i)=i(2n-i+1)/2
        float s = sqrtf(fn2 * fn2 - 8.0f * (float)p);
        int   i = (int)((fn2 - s) * 0.5f);
        int   Ri = (i * (2 * n - i + 1)) >> 1;
        if (p < Ri)            { i--; Ri = (i * (2 * n - i + 1)) >> 1; }
        else { int Rn = ((i + 1) * (2 * n - i)) >> 1;
               if (p >= Rn)    { i++; Ri = Rn; } }
        int j = i + (p - Ri);

        float2 ei = se[i], ej = se[j];
        unsigned int ai = swl[i], aj = swl[j];
        int wi = (int)(ai & 0xFFu), li = (int)(ai >> 8);
        int wj = (int)(aj & 0xFFu), lj = (int)(aj >> 8);

        int d = li - lj; d = d < 0 ? -d : d;
        float wgt = dvals[d] * fminf(ei.x * ej.y, ei.y * ej.x);
        if (i == j)            wgt = 1.0f;      // exact: D[l,l]=1, dt=0
        else if (wi == wj)     wgt *= 2.0f;     // both orientations hit same cell

        int c1 = min(wi, wj), c2 = max(wi, wj);
        atomicAdd(&accb[c1 * 128 + c2], wgt);   // RED (no return)
    }
}

// ---------------- finalize: tanh + mirror + re-zero state for next replay ----------------
__global__ __launch_bounds__(256)
void finalize_kernel(float* __restrict__ out)
{
    const int gid = blockIdx.x * 256 + threadIdx.x;   // 0..131071
    if (gid < NBKT) g_cnt[gid] = 0;

    const int b   = gid >> 14;
    const int rem = gid & 16383;
    const int c1  = rem >> 7;
    const int c2  = rem & 127;
    if (c1 > c2) return;                // non-canonical cells are never written

    float a = g_acc[gid];
    g_acc[gid] = 0.0f;                  // clean for next launch/replay
    float v = tanhf(fminf(a, 10.0f));   // a >= 0
    out[gid] = v;
    out[(b * 128 + c2) * 128 + c1] = v;
}

extern "C" void kernel_launch(void* const* d_in, const int* in_sizes, int n_in,
                              void* d_out, int out_size)
{
    const void*  nodes = d_in[0];
    const void*  masks = d_in[1];
    const float* times = (const float*)d_in[2];
    float*       out   = (float*)d_out;

    prep_kernel<<<TOTPOS / BPREP, BPREP>>>(nodes, masks, times);
    pairs_kernel<<<NBKT * 2, 256>>>();
    finalize_kernel<<<131072 / 256, 256>>>(out);
}

// round 6
// speedup vs baseline: 1.0555x; 1.0555x over previous
#include <cuda_runtime.h>
#include <cuda_bf16.h>
#include <cstdint>

// TemporalCooccurrenceMatrix — round 6: bucket pair-list, contention-free prep.
//
// C[b,w1,w2] = sum over valid same-node position pairs of
//              e^{-(l1-l2)^2/4} * e^{-|t1-t2|/5};  out = tanh(min(C,10)).
// prep:     16 CTAs (batch x half). smem counters assign bucket slots; entries
//           (e^{+t/5},e^{-t/5}) + packed (w,l) stored to per-(bucket,half) segments.
//           Counts written with plain stores (CTA-owned) -> self-cleaning.
// pairs:    1 CTA per bucket. Rows -> warps, lanes sweep j>=i. Uniform flow,
//           no MUFU, one RED per canonical pair into g_acc upper triangle.
// finalize: tanh + mirror + re-zero g_acc for the next graph replay.

#define NBKT 256      // 8 batches * 32 node values
#define HALFC 80      // capacity per (bucket, half): mean 32, +8.6 sd
#define BCAP  (2 * HALFC)

__device__ float        g_acc[131072];        // [8][128][128], canonical c1<=c2 only
__device__ int          g_cnt[NBKT * 2];      // per (bucket, half) count
__device__ float2       g_be [NBKT * BCAP];   // (e^{+t/5}, e^{-t/5})
__device__ unsigned int g_bwl[NBKT * BCAP];   // w | (l<<8)

// ---------------- prep ----------------
__global__ __launch_bounds__(256)
void prep_kernel(const void* __restrict__ nodes_raw,
                 const void* __restrict__ masks_raw,
                 const float* __restrict__ times)
{
    __shared__ int s_n64, s_m32;
    __shared__ int cnt[32];

    if (threadIdx.x < 32) {
        cnt[threadIdx.x] = 0;
        // dtype detection, one L2 round trip (ballot):
        const unsigned int*  nw = (const unsigned int*)nodes_raw;
        const unsigned char* mb = (const unsigned char*)masks_raw;
        int lane = threadIdx.x;
        unsigned int oddw = nw[2 * lane + 1];             // int64 LE hi words all 0
        unsigned char b0 = mb[lane], b1 = mb[32 + lane];  // int32-bool: k%4!=0 bytes 0
        int nviol = (oddw != 0u);
        int mviol = (((lane & 3) != 0) && b0 != 0) |
                    ((((32 + lane) & 3) != 0) && b1 != 0);
        unsigned int vn = __ballot_sync(0xFFFFFFFFu, nviol);
        unsigned int vm = __ballot_sync(0xFFFFFFFFu, mviol);
        if (lane == 0) { s_n64 = (vn == 0u); s_m32 = (vm == 0u); }
    }
    __syncthreads();

    const int batch = blockIdx.x >> 1;
    const int sub   = blockIdx.x & 1;
    const int tid   = threadIdx.x;
    const int n64   = s_n64, m32 = s_m32;

    const unsigned int*  n32p = (const unsigned int*)nodes_raw;
    const unsigned char* mbp  = (const unsigned char*)masks_raw;
    const unsigned int*  m32p = (const unsigned int*)masks_raw;

    const int base = batch * 2560 + sub * 1280;
#pragma unroll
    for (int k = 0; k < 5; k++) {
        const int i = base + k * 256 + tid;          // global flat position
        bool m = m32 ? (m32p[i] != 0u) : (mbp[i] != 0);
        if (!m) continue;
        int v = (int)(n64 ? n32p[i * 2] : n32p[i]) & 31;
        int slot = atomicAdd(&cnt[v], 1);            // smem, spread addresses
        if (slot < HALFC) {
            int rel = i - batch * 2560;
            int w = rel / 20, l = rel - w * 20;
            int gi = (batch * 32 + v) * BCAP + sub * HALFC + slot;
            float t = times[i] * 0.2f;
            g_be [gi] = make_float2(__expf(t), __expf(-t));
            g_bwl[gi] = (unsigned int)w | ((unsigned int)l << 8);
        }
    }
    __syncthreads();
    if (tid < 32)
        g_cnt[(batch * 32 + tid) * 2 + sub] = min(cnt[tid], HALFC);
}

// ---------------- pairs ----------------
__global__ __launch_bounds__(256)
void pairs_kernel()
{
    const int bkt = blockIdx.x;          // 0..255
    const int b   = bkt >> 5;
    const int tid = threadIdx.x;

    __shared__ float2       se [BCAP];
    __shared__ unsigned int swl[BCAP];
    __shared__ float        dvals[20];
    __shared__ int s_n0, s_n1;

    if (tid == 0) { s_n0 = g_cnt[bkt * 2]; s_n1 = g_cnt[bkt * 2 + 1]; }
    if (tid < 20) dvals[tid] = __expf(-0.25f * (float)(tid * tid));
    __syncthreads();

    const int n0 = s_n0, n = n0 + s_n1;
    for (int k = tid; k < n; k += 256) {
        int src = bkt * BCAP + (k < n0 ? k : HALFC + (k - n0));
        se[k]  = g_be [src];
        swl[k] = g_bwl[src];
    }
    __syncthreads();

    float* accb = g_acc + b * 16384;
    const int wid = tid >> 5, lane = tid & 31;

    for (int i = wid; i < n; i += 8) {
        const float2 ei = se[i];
        const unsigned int ai = swl[i];
        const int wi = (int)(ai & 0xFFu), li = (int)(ai >> 8);
        for (int j = i + lane; j < n; j += 32) {
            float2 ej = se[j];
            unsigned int aj = swl[j];
            int wj = (int)(aj & 0xFFu), lj = (int)(aj >> 8);
            int d = li - lj; d = d < 0 ? -d : d;
            float wgt = dvals[d] * fminf(ei.x * ej.y, ei.y * ej.x);
            if (j == i)          wgt = 1.0f;    // exact diagonal term
            else if (wi == wj)   wgt *= 2.0f;   // both orientations, same cell
            int c1 = min(wi, wj), c2 = max(wi, wj);
            atomicAdd(&accb[c1 * 128 + c2], wgt);   // RED (no return)
        }
    }
}

// ---------------- finalize ----------------
__global__ __launch_bounds__(256)
void finalize_kernel(float* __restrict__ out)
{
    const int gid = blockIdx.x * 256 + threadIdx.x;   // 0..131071
    const int b   = gid >> 14;
    const int rem = gid & 16383;
    const int c1  = rem >> 7;
    const int c2  = rem & 127;
    if (c1 > c2) return;                // never written, stays 0

    float a = g_acc[gid];
    g_acc[gid] = 0.0f;                  // clean for next replay
    float v = tanhf(fminf(a, 10.0f));   // a >= 0
    out[gid] = v;
    out[(b * 128 + c2) * 128 + c1] = v;
}

extern "C" void kernel_launch(void* const* d_in, const int* in_sizes, int n_in,
                              void* d_out, int out_size)
{
    const void*  nodes = d_in[0];
    const void*  masks = d_in[1];
    const float* times = (const float*)d_in[2];
    float*       out   = (float*)d_out;

    prep_kernel<<<16, 256>>>(nodes, masks, times);
    pairs_kernel<<<NBKT, 256>>>();
    finalize_kernel<<<131072 / 256, 256>>>(out);
}

// round 7
// speedup vs baseline: 1.1131x; 1.0546x over previous
#include <cuda_runtime.h>
#include <cuda_bf16.h>
#include <cstdint>

// TemporalCooccurrenceMatrix — round 7: fused bucket-build + pairs (no prep stage).
//
// C[b,w1,w2] = sum over valid same-node position pairs of
//              e^{-(l1-l2)^2/4} * e^{-|t1-t2|/5};   out = tanh(min(C,10)).
//
// kernel 1 (256 CTAs = one per (batch, node-value) bucket):
//   - dtype-detect (int64-vs-int32 nodes, bool-vs-int32 masks) via one warp ballot
//   - scan the batch's 2560 positions, warp-ballot-compact matches into smem
//     (entry: (e^{+t/5}, e^{-t/5}), packed (w,l)); ~64 members, 2 __expf each
//   - uniform-flow triangular pair sweep (rows->warps, lanes->j), one RED per
//     canonical pair into g_acc upper triangle
// kernel 2: tanh + symmetric mirror + re-zero g_acc for the next graph replay.
// g_acc is static-zero-init for call 1; finalize re-zeros it for replays.

#define BCAPF 192     // bucket capacity: mean 64, sd ~7.9 -> +16 sd headroom

__device__ float g_acc[131072];   // [8][128][128], canonical c1<=c2 cells only

__global__ __launch_bounds__(256)
void bucket_pairs_kernel(const void* __restrict__ nodes_raw,
                         const void* __restrict__ masks_raw,
                         const float* __restrict__ times)
{
    const int bkt = blockIdx.x;        // 0..255
    const int b   = bkt >> 5;          // batch
    const int v   = bkt & 31;          // node value
    const int tid = threadIdx.x;
    const int wid = tid >> 5, lane = tid & 31;

    __shared__ float2       se [BCAPF];   // (e^{+t/5}, e^{-t/5})
    __shared__ unsigned int swl[BCAPF];   // w | (l<<8)
    __shared__ float        dvals[20];    // exp(-d^2/4)
    __shared__ int          scnt;
    __shared__ int          s_n64, s_m32;

    // ---- dtype detection: one L2 round trip, warp 0 ----
    if (tid < 32) {
        const unsigned int*  nw = (const unsigned int*)nodes_raw;
        const unsigned char* mb = (const unsigned char*)masks_raw;
        unsigned int oddw = nw[2 * tid + 1];             // int64 LE hi words all 0
        unsigned char b0 = mb[tid], b1 = mb[32 + tid];   // int32-bool: k%4!=0 bytes 0
        int nviol = (oddw != 0u);
        int mviol = (((tid & 3) != 0) && b0 != 0) |
                    ((((32 + tid) & 3) != 0) && b1 != 0);
        unsigned int vn = __ballot_sync(0xFFFFFFFFu, nviol);
        unsigned int vm = __ballot_sync(0xFFFFFFFFu, mviol);
        if (tid == 0) { s_n64 = (vn == 0u); s_m32 = (vm == 0u); scnt = 0; }
    }
    if (tid < 20) dvals[tid] = __expf(-0.25f * (float)(tid * tid));
    __syncthreads();

    const int n64 = s_n64, m32 = s_m32;
    const unsigned int*  n32p = (const unsigned int*)nodes_raw;
    const unsigned char* mbp  = (const unsigned char*)masks_raw;
    const unsigned int*  m32p = (const unsigned int*)masks_raw;

    // ---- scan + warp-ballot compaction into smem bucket ----
    const int base = b * 2560;
#pragma unroll
    for (int k = 0; k < 10; k++) {
        const int pos = k * 256 + tid;       // 0..2559 within batch
        const int i   = base + pos;
        bool m  = m32 ? (m32p[i] != 0u) : (mbp[i] != 0);
        int  nv = (int)(n64 ? n32p[i * 2] : n32p[i]) & 31;
        bool match = m && (nv == v);

        unsigned int bal = __ballot_sync(0xFFFFFFFFu, match);
        if (bal) {
            int wbase = 0;
            if (lane == 0) wbase = atomicAdd(&scnt, __popc(bal));
            wbase = __shfl_sync(0xFFFFFFFFu, wbase, 0);
            if (match) {
                int off = wbase + __popc(bal & ((1u << lane) - 1u));
                if (off < BCAPF) {
                    int w = pos / 20, l = pos - w * 20;
                    float t = times[i] * 0.2f;
                    se [off] = make_float2(__expf(t), __expf(-t));
                    swl[off] = (unsigned int)w | ((unsigned int)l << 8);
                }
            }
        }
    }
    __syncthreads();
    const int n = min(scnt, BCAPF);

    // ---- triangular pair sweep: rows -> warps, lanes -> j ----
    float* accb = g_acc + b * 16384;
    for (int i = wid; i < n; i += 8) {
        const float2 ei = se[i];
        const unsigned int ai = swl[i];
        const int wi = (int)(ai & 0xFFu), li = (int)(ai >> 8);
        for (int j = i + lane; j < n; j += 32) {
            float2 ej = se[j];
            unsigned int aj = swl[j];
            int wj = (int)(aj & 0xFFu), lj = (int)(aj >> 8);
            int d = li - lj; d = d < 0 ? -d : d;
            float wgt = dvals[d] * fminf(ei.x * ej.y, ei.y * ej.x);
            if (j == i)          wgt = 1.0f;    // exact diagonal: D=1, dt=0
            else if (wi == wj)   wgt *= 2.0f;   // both orientations, same cell
            int c1 = min(wi, wj), c2 = max(wi, wj);
            atomicAdd(&accb[c1 * 128 + c2], wgt);   // RED (no return)
        }
    }
}

__global__ __launch_bounds__(256)
void finalize_kernel(float* __restrict__ out)
{
    const int gid = blockIdx.x * 256 + threadIdx.x;   // 0..131071
    const int b   = gid >> 14;
    const int rem = gid & 16383;
    const int c1  = rem >> 7;
    const int c2  = rem & 127;
    if (c1 > c2) return;                // never written, stays 0

    float a = g_acc[gid];
    g_acc[gid] = 0.0f;                  // clean for next graph replay
    float vv = tanhf(fminf(a, 10.0f));  // a >= 0
    out[gid] = vv;
    out[(b * 128 + c2) * 128 + c1] = vv;
}

extern "C" void kernel_launch(void* const* d_in, const int* in_sizes, int n_in,
                              void* d_out, int out_size)
{
    const void*  nodes = d_in[0];
    const void*  masks = d_in[1];
    const float* times = (const float*)d_in[2];
    float*       out   = (float*)d_out;

    bucket_pairs_kernel<<<256, 256>>>(nodes, masks, times);
    finalize_kernel<<<131072 / 256, 256>>>(out);
}

// round 9
// speedup vs baseline: 1.4870x; 1.3359x over previous
#include <cuda_runtime.h>
#include <cuda_bf16.h>
#include <cstdint>

// TemporalCooccurrenceMatrix — round 9 (R8 resubmit after infra failure):
// R4 structure (register accumulation, no scattered atomics) + predicated
// 2-slot inner loop (divergence-free for 98.6% of positions; rare fallback
// for match multiplicity >= 3).
//
// C[b,w1,w2] = sum_{l1,l2} [node==][mask&mask] * e^{-(l1-l2)^2/4}*e^{-|t1-t2|/5}
// out = tanh(min(C,10)); symmetric -> rows r and 127-r paired per CTA (512 CTAs).
// e^{-|a-b|/5} = min(e^{a/5}e^{-b/5}, e^{-a/5}e^{b/5}); prep precomputes
// (e^{+t/5},e^{-t/5}) and padded node bytes (32 = masked/pad sentinel).

#define TOT   20480            // 8*128*20
#define PTOT  32768            // 8*128*32 padded node bytes (16 per half)
#define BPREP 256
#define BDIM  288              // 2 threads x 129 targets = 258 active

__device__ __align__(16) float2        g_e2[TOT];   // (e^{+t/5}, e^{-t/5})
__device__ __align__(16) unsigned char g_pnp[PTOT]; // node 0..31, 32 = invalid

__global__ __launch_bounds__(BPREP)
void prep_kernel(const void* __restrict__ nodes_raw,
                 const void* __restrict__ masks_raw,
                 const float* __restrict__ times)
{
    __shared__ int s_n64, s_m32;
    if (threadIdx.x < 32) {
        const unsigned int*  nw = (const unsigned int*)nodes_raw;
        const unsigned char* mb = (const unsigned char*)masks_raw;
        int lane = threadIdx.x;
        unsigned int oddw = nw[2 * lane + 1];             // int64 LE hi words all 0
        unsigned char b0 = mb[lane], b1 = mb[32 + lane];  // int32-bool: k%4!=0 zero
        int nviol = (oddw != 0u);
        int mviol = (((lane & 3) != 0) && b0 != 0) |
                    ((((32 + lane) & 3) != 0) && b1 != 0);
        unsigned int vn = __ballot_sync(0xFFFFFFFFu, nviol);
        unsigned int vm = __ballot_sync(0xFFFFFFFFu, mviol);
        if (lane == 0) { s_n64 = (vn == 0u); s_m32 = (vm == 0u); }
    }
    __syncthreads();

    const int idx = blockIdx.x * BPREP + threadIdx.x;   // padded index
    if (idx >= PTOT) return;
    const int walk = idx >> 5;
    const int s    = idx & 31;
    const int half = s >> 4;
    const int k    = s & 15;

    if (k >= 10) { g_pnp[idx] = 32; return; }           // pad slots

    const int i = walk * 20 + half * 10 + k;            // real flat position
    const unsigned int*  n32p = (const unsigned int*)nodes_raw;
    const unsigned char* mbp  = (const unsigned char*)masks_raw;
    const unsigned int*  m32p = (const unsigned int*)masks_raw;

    int  v = (int)(s_n64 ? n32p[i * 2] : n32p[i]) & 31;
    bool m = s_m32 ? (m32p[i] != 0u) : (mbp[i] != 0);
    g_pnp[idx] = m ? (unsigned char)v : (unsigned char)32;

    float t = times[i] * 0.2f;
    g_e2[i] = make_float2(__expf(t), __expf(-t));
}

__global__ __launch_bounds__(BDIM)
void cooc_kernel(float* __restrict__ out)
{
    const int r   = blockIdx.x;   // 0..63
    const int b   = blockIdx.y;   // 0..7
    const int tid = threadIdx.x;

    const int wA = r, wB = 127 - r;
    const int nA = 128 - r;       // row-A targets (w2 in [r,127]); nB = r+1

    __shared__ float        dvals[32];          // exp(-d^2/4), 0 for d>=20
    __shared__ unsigned int nmA[33], nmB[33];   // [32] stays 0 (sentinel)
    __shared__ float2       sA[32], sB[32];     // entries >=20 are (0,0)
    __shared__ float        acc[129];

    if (tid < 32) {
        dvals[tid] = (tid < 20) ? __expf(-0.25f * (float)(tid * tid)) : 0.0f;
        sA[tid] = make_float2(0.0f, 0.0f);
        sB[tid] = make_float2(0.0f, 0.0f);
        nmA[tid] = 0u; nmB[tid] = 0u;
    }
    if (tid == 32) { nmA[32] = 0u; nmB[32] = 0u; }
    if (tid >= 64 && tid < 64 + 129) acc[tid - 64] = 0.0f;
    __syncthreads();

    if (tid < 20) {
        int l = tid;
        int pslot = (b * 128 + wA) * 32 + (l >= 10 ? 16 + (l - 10) : l);
        int v = g_pnp[pslot];
        sA[l] = g_e2[(b * 128 + wA) * 20 + l];
        if (v < 32) atomicOr(&nmA[v], 1u << l);
    } else if (tid >= 32 && tid < 52) {
        int l = tid - 32;
        int pslot = (b * 128 + wB) * 32 + (l >= 10 ? 16 + (l - 10) : l);
        int v = g_pnp[pslot];
        sB[l] = g_e2[(b * 128 + wB) * 20 + l];
        if (v < 32) atomicOr(&nmB[v], 1u << l);
    }
    __syncthreads();

    const int pair = tid >> 1;        // 0..143 (129 real targets)
    const int half = tid & 1;
    const bool active = (pair < 129);
    const bool rowA   = active ? (pair < nA) : true;
    int w2 = rowA ? (wA + (active ? pair : 0)) : (wB + (pair - nA));
    if (!active) w2 = 127;            // safe in-bounds addresses; result discarded

    const unsigned int* NM = rowA ? nmA : nmB;
    const float2*       S  = rowA ? sA  : sB;

    // prefetch: 10 node bytes (1 x LDG.128, padded layout) + 10 float2 (5 x LDG.128)
    const uint4 pn4 = *(const uint4*)&g_pnp[(b * 128 + w2) * 32 + half * 16];
    const float4* ep = (const float4*)(g_e2 + (b * 128 + w2) * 20 + half * 10);
    float4 e4[5];
#pragma unroll
    for (int q = 0; q < 5; q++) e4[q] = ep[q];
    const unsigned int pw[4] = { pn4.x, pn4.y, pn4.z, pn4.w };

    const int ljbase = half * 10;
    float a = 0.0f;
#pragma unroll
    for (int k = 0; k < 10; k++) {
        const float4 f = e4[k >> 1];
        const float ex = (k & 1) ? f.z : f.x;
        const float ey = (k & 1) ? f.w : f.y;
        const unsigned int vk = (pw[k >> 2] >> ((k & 3) * 8)) & 0xFFu;
        unsigned int bits = NM[vk];
        const int lj = ljbase + k;

        // two inline slots; empty slot -> li=-1 -> S[31]=(0,0) and dvals[<=20]=0
        int li0 = __ffs(bits) - 1;
        unsigned int b1 = bits & (bits - 1);
        int li1 = __ffs(b1) - 1;
        unsigned int rest = b1 & (b1 - 1);
        {
            float2 sv = S[li0 & 31];
            int d = li0 - lj; d = d < 0 ? -d : d;
            a += dvals[d] * fminf(ex * sv.y, ey * sv.x);
        }
        {
            float2 sv = S[li1 & 31];
            int d = li1 - lj; d = d < 0 ? -d : d;
            a += dvals[d] * fminf(ex * sv.y, ey * sv.x);
        }
        if (rest) {                    // multiplicity >= 3: ~1.4% of positions
#pragma unroll 1
            do {
                int li = __ffs(rest) - 1;
                rest &= rest - 1;
                float2 sv = S[li];
                int d = li - lj; d = d < 0 ? -d : d;
                a += dvals[d] * fminf(ex * sv.y, ey * sv.x);
            } while (rest);
        }
    }

    // combine the two halves of each target (adjacent lanes), single plain store
    a += __shfl_xor_sync(0xFFFFFFFFu, a, 1);
    if (active && half == 0) acc[pair] = a;
    __syncthreads();

    if (tid < 129) {
        const bool rA = (tid < nA);
        const int  w1 = rA ? wA : wB;
        const int  wc = rA ? (wA + tid) : (wB + (tid - nA));
        float v = tanhf(fminf(acc[tid], 10.0f));   // acc >= 0
        out[(b * 128 + w1) * 128 + wc] = v;
        out[(b * 128 + wc) * 128 + w1] = v;
    }
}

extern "C" void kernel_launch(void* const* d_in, const int* in_sizes, int n_in,
                              void* d_out, int out_size)
{
    const void*  nodes = d_in[0];
    const void*  masks = d_in[1];
    const float* times = (const float*)d_in[2];
    float*       out   = (float*)d_out;

    prep_kernel<<<PTOT / BPREP, BPREP>>>(nodes, masks, times);
    dim3 grid(64, 8);
    cooc_kernel<<<grid, BDIM>>>(out);
}